// round 4
// baseline (speedup 1.0000x reference)
#include <cuda_runtime.h>
#include <math.h>

// AttentionAggregator: 2 warps per row, register-resident halves.
// features: [100000, 256] f32; nodes: [4096] i32; unique_ids: [16384] i32;
// neigh_idx: [4096, 10] i32. out: [4096, 256] f32.
//
// Warp pair (2 warps) owns one node row; each warp holds 128 of the 256 dims
// (one float4 per lane per embed row -> 44 data regs instead of 88). Partial
// dot products are combined through shared memory with a single
// __syncthreads(); softmax (with duplicate-column dedup, matching the dense
// mask's .set(1.0) semantics) is computed redundantly on every lane;
// aggregation is pure register FMA with no reloads.

#define N_NODES 4096
#define FDIM    256
#define NSAMP   10
#define WARPS_PER_BLOCK 8           // 4 rows per block
#define ROWS_PER_BLOCK  (WARPS_PER_BLOCK / 2)

__global__ __launch_bounds__(WARPS_PER_BLOCK * 32, 3)
void attn_agg_kernel(const float* __restrict__ feat,
                     const int*   __restrict__ nodes,
                     const int*   __restrict__ uids,
                     const int*   __restrict__ nidx,
                     float*       __restrict__ out)
{
    const int warp  = threadIdx.x >> 5;
    const int lane  = threadIdx.x & 31;
    const int rloc  = warp >> 1;          // row within block
    const int half  = warp & 1;           // which 128-dim half
    const int row   = blockIdx.x * ROWS_PER_BLOCK + rloc;

    __shared__ float sdots[ROWS_PER_BLOCK][2][NSAMP];

    // --- index gathers (warp-uniform, independent) ---
    int cols[NSAMP];
    #pragma unroll
    for (int s = 0; s < NSAMP; s++)
        cols[s] = nidx[row * NSAMP + s];

    int uid[NSAMP];
    #pragma unroll
    for (int s = 0; s < NSAMP; s++)
        uid[s] = uids[cols[s]];

    // Duplicate-column mask (dense mask counts repeated (row,col) once).
    unsigned dupmask = 0;
    #pragma unroll
    for (int s = 1; s < NSAMP; s++) {
        bool d = false;
        #pragma unroll
        for (int t = 0; t < NSAMP; t++)
            if (t < s) d |= (cols[t] == cols[s]);
        if (d) dupmask |= (1u << s);
    }

    const int node = nodes[row];
    const int off  = lane + 32 * half;    // float4 index within the 256-dim row

    // --- bulk loads: q half-row + 10 embed half-rows (11x LDG.128, independent)
    const float4 q = ((const float4*)(feat + (size_t)node * FDIM))[off];

    float4 r[NSAMP];
    #pragma unroll
    for (int s = 0; s < NSAMP; s++)
        r[s] = ((const float4*)(feat + (size_t)uid[s] * FDIM))[off];

    // --- partial dots over this half, warp-reduced ---
    #pragma unroll
    for (int s = 0; s < NSAMP; s++) {
        float a = r[s].x * q.x + r[s].y * q.y + r[s].z * q.z + r[s].w * q.w;
        #pragma unroll
        for (int o = 16; o; o >>= 1)
            a += __shfl_xor_sync(0xffffffffu, a, o);
        if (lane == 0) sdots[rloc][half][s] = a;
    }
    __syncthreads();

    // --- combine halves, softmax over distinct columns (redundant per lane) ---
    float w[NSAMP];
    float m = -INFINITY;
    #pragma unroll
    for (int s = 0; s < NSAMP; s++) {
        w[s] = sdots[rloc][0][s] + sdots[rloc][1][s];
        if (!((dupmask >> s) & 1u)) m = fmaxf(m, w[s]);
    }
    float sum = 0.f;
    #pragma unroll
    for (int s = 0; s < NSAMP; s++) {
        float e = ((dupmask >> s) & 1u) ? 0.f : __expf(w[s] - m);
        w[s] = e;
        sum += e;
    }
    const float inv = 1.f / sum;

    // --- aggregation: pure register FMA, one STG.128 per lane ---
    float4 o = make_float4(0.f, 0.f, 0.f, 0.f);
    #pragma unroll
    for (int s = 0; s < NSAMP; s++) {
        const float ws = w[s] * inv;
        o.x += ws * r[s].x;
        o.y += ws * r[s].y;
        o.z += ws * r[s].z;
        o.w += ws * r[s].w;
    }
    ((float4*)(out + (size_t)row * FDIM))[off] = o;
}

extern "C" void kernel_launch(void* const* d_in, const int* in_sizes, int n_in,
                              void* d_out, int out_size)
{
    const float* feat  = (const float*)d_in[0];
    const int*   nodes = (const int*)  d_in[1];
    const int*   uids  = (const int*)  d_in[2];
    const int*   nidx  = (const int*)  d_in[3];
    float*       out   = (float*)d_out;
    (void)in_sizes; (void)n_in; (void)out_size;

    attn_agg_kernel<<<N_NODES / ROWS_PER_BLOCK, WARPS_PER_BLOCK * 32>>>(
        feat, nodes, uids, nidx, out);
}